// round 7
// baseline (speedup 1.0000x reference)
#include <cuda_runtime.h>

// SSIM, fully fused, separable 11-tap Gaussian, streaming vertical ring accumulators.
// Layout: 48 planes (16 batch x 3 ch) of 512x512 fp32.
// Grid: plane x 4 column-strips (128 cols) x 4 row-bands (128 rows) = 768 blocks.
// Block: 128 threads, thread t owns column c0+t of its strip.

#define IMG_H 512
#define IMG_W 512
#define NPLANES 48
#define TW 128
#define BAND 128
#define SROW 144            // padded smem row (need 138)
#define NCHUNKS 13          // 13*11 = 143 input rows per band (need 138)
#define C1F 0.0001f         // 0.01^2
#define C2F 0.0009f         // 0.03^2
#define INV_TOTAL (1.0 / 12582912.0)

__device__ double g_ssim_accum;

__global__ void ssim_zero_kernel() { g_ssim_accum = 0.0; }

__global__ void ssim_finalize_kernel(float* out) {
    out[0] = (float)(g_ssim_accum * INV_TOTAL);
}

__global__ void __launch_bounds__(128, 4) ssim_main_kernel(
    const float* __restrict__ img1,
    const float* __restrict__ img2)
{
    const int tid   = threadIdx.x;
    const int bx    = blockIdx.x;
    const int strip = bx & 3;
    const int band  = (bx >> 2) & 3;
    const int plane = bx >> 4;

    const int c0 = strip * TW;
    const int R0 = band * BAND;
    const long planeOff = (long)plane * (IMG_H * IMG_W);
    const float* __restrict__ p1 = img1 + planeOff;
    const float* __restrict__ p2 = img2 + planeOff;

    __shared__ float s1[11][SROW];
    __shared__ float s2[11][SROW];

    // 1D Gaussian weights (sigma=1.5, K=11), normalized; compile-time constants
    // so vertical FFMAs take the immediate form (rt=1 on sm_103a).
    const float WW[11] = {
        0.00102838f, 0.00759876f, 0.03600077f, 0.10936069f, 0.21300554f,
        0.26601172f,
        0.21300554f, 0.10936069f, 0.03600077f, 0.00759876f, 0.00102838f
    };

    // Ring accumulators: slot j holds output row o with (o - ir0) mod 11 == j.
    float a1[11], a2[11], a11[11], a22[11], a12[11];
#pragma unroll
    for (int j = 0; j < 11; j++) {
        a1[j] = 0.f; a2[j] = 0.f; a11[j] = 0.f; a22[j] = 0.f; a12[j] = 0.f;
    }

    float ssum = 0.f;
    const int ir0 = R0 - 5;   // first input row needed

    for (int chunk = 0; chunk < NCHUNKS; chunk++) {
        __syncthreads();   // previous chunk's compute done before overwriting smem
        // Stage 11 input rows (with horizontal halo, zero padded) for both images.
        const int baseRow = ir0 + chunk * 11;
        for (int i = tid; i < 11 * 138; i += 128) {
            const int u  = i / 138;
            const int cc = i - u * 138;
            const int r  = baseRow + u;
            const int c  = c0 - 5 + cc;
            float v1 = 0.f, v2 = 0.f;
            if (r >= 0 && r < IMG_H && c >= 0 && c < IMG_W) {
                const int idx = r * IMG_W + c;
                v1 = p1[idx];
                v2 = p2[idx];
            }
            s1[u][cc] = v1;
            s2[u][cc] = v2;
        }
        __syncthreads();

#pragma unroll
        for (int u = 0; u < 11; u++) {
            // ---- horizontal separable conv of the 5 fields for this row ----
            float h1 = 0.f, h2 = 0.f, h11 = 0.f, h22 = 0.f, h12 = 0.f;
#pragma unroll
            for (int k = 0; k < 11; k++) {
                const float a  = s1[u][tid + k];
                const float b  = s2[u][tid + k];
                const float ta = WW[k] * a;
                const float tb = WW[k] * b;
                h1 += ta;
                h2 += tb;
                h11 = fmaf(ta, a, h11);
                h22 = fmaf(tb, b, h22);
                h12 = fmaf(ta, b, h12);
            }
            // ---- vertical scatter into ring accumulators (static indices) ----
#pragma unroll
            for (int j = 0; j < 11; j++) {
                const int k = (u + 5 - j + 11) % 11;   // compile-time per (u,j)
                a1[j]  = fmaf(WW[k], h1,  a1[j]);
                a2[j]  = fmaf(WW[k], h2,  a2[j]);
                a11[j] = fmaf(WW[k], h11, a11[j]);
                a22[j] = fmaf(WW[k], h22, a22[j]);
                a12[j] = fmaf(WW[k], h12, a12[j]);
            }
            // ---- output row o = R0 + t - 10 completes this iteration ----
            const int jc = (u + 6) % 11;               // compile-time per u
            const int t  = chunk * 11 + u;
            if (t >= 10 && t < 138) {
                const float mu1   = a1[jc];
                const float mu2   = a2[jc];
                const float mu1sq = mu1 * mu1;
                const float mu2sq = mu2 * mu2;
                const float mu12  = mu1 * mu2;
                const float sg1   = a11[jc] - mu1sq;
                const float sg2   = a22[jc] - mu2sq;
                const float sg12  = a12[jc] - mu12;
                const float num = (2.f * mu12 + C1F) * (2.f * sg12 + C2F);
                const float den = (mu1sq + mu2sq + C1F) * (sg1 + sg2 + C2F);
                ssum += __fdividef(num, den);
            }
            a1[jc] = 0.f; a2[jc] = 0.f; a11[jc] = 0.f; a22[jc] = 0.f; a12[jc] = 0.f;
        }
    }

    // ---- reduction: warp shfl -> block -> one double atomic per block ----
#pragma unroll
    for (int off = 16; off; off >>= 1)
        ssum += __shfl_xor_sync(0xffffffffu, ssum, off);

    __shared__ float wsum[4];
    if ((tid & 31) == 0) wsum[tid >> 5] = ssum;
    __syncthreads();
    if (tid == 0) {
        const double bsum = (double)wsum[0] + (double)wsum[1]
                          + (double)wsum[2] + (double)wsum[3];
        atomicAdd(&g_ssim_accum, bsum);
    }
}

extern "C" void kernel_launch(void* const* d_in, const int* in_sizes, int n_in,
                              void* d_out, int out_size) {
    const float* img1 = (const float*)d_in[0];
    const float* img2 = (const float*)d_in[1];
    // d_in[2] (window) is unused: weights are baked in as compile-time constants.
    float* out = (float*)d_out;

    ssim_zero_kernel<<<1, 1>>>();
    ssim_main_kernel<<<NPLANES * 16, 128>>>(img1, img2);
    ssim_finalize_kernel<<<1, 1>>>(out);
}